// round 4
// baseline (speedup 1.0000x reference)
#include <cuda_runtime.h>
#include <math.h>
#include <cstdint>

#define N    3072
#define NT   1024
#define PER  3       // N / NT
#define NW   32      // warps per block

static_assert(NT * PER == N, "layout");

// f32(pi/2) = 0x3FC90FDB — the reference's ANGLE_THR after f32 weak-type cast.
#define ANGLE_THR_BITS 0x3FC90FDB

// All working state lives in shared memory of ONE persistent block.
struct SmemLayout {
    float px[N], py[N], pz[N];     // points (px region reused as sort keys later)
    int   slbl[N];                 // per-point class labels
    int   sdl[N];                  // per-point cluster label (scan output)
    float ccx[N], ccy[N], ccz[N];  // per-cluster centres
    int   ccount[N];               // per-cluster sizes
    int   ccls[N];                 // per-cluster class
    int   order[N];                // order position -> cluster id
    int   items[N];                // per-class concatenated lists of order-positions
    int   remap[N];                // cluster id -> final cluster id after merge
    unsigned char keep[N];         // per order-position keep flag
    unsigned long long rpack[NW];  // reduction scratch (argmin pack)
    float rmin[NW], rmax[NW], rxm[NW]; // reduction scratch
    float amdxy[10], amdz[10], ar2[10];  // anchor-derived constants
    int   clsCount[10], clsBase[11];
    // broadcast state (written by serial thread)
    int   bci, bcls, bnc, blab;
    float bpcx, bpcy, bpcz, bdmin, bdmax, bpn, bxmin;
};

// XLA-order 3D norm: sqrt(((x*x + y*y) + z*z)), no FMA contraction.
__device__ __forceinline__ float norm3_xla(float x, float y, float z) {
    float s = __fadd_rn(__fadd_rn(__fmul_rn(x, x), __fmul_rn(y, y)), __fmul_rn(z, z));
    return __fsqrt_rn(s);
}

// lax.acos lowering: acos(x) = 2*atan2(sqrt(1-x*x), 1+x), x != -1; pi at -1.
// Both the reference (XLA -> libdevice) and this kernel (nvcc -> libdevice) hit
// the same __nv_atan2f, so the result matches the reference bit-for-bit.
__device__ __forceinline__ float acos_xla(float x) {
    float s = __fsqrt_rn(__fsub_rn(1.0f, __fmul_rn(x, x)));
    float r = 2.0f * atan2f(s, __fadd_rn(1.0f, x));
    if (x == -1.0f) r = __int_as_float(0x40490FDB); // f32 pi
    return r;
}

__global__ void __launch_bounds__(NT, 1)
frustum_cluster_kernel(const float* __restrict__ pts,
                       const int*   __restrict__ lbl,
                       const float* __restrict__ anchors,
                       float* __restrict__ out)
{
    extern __shared__ char raw[];
    SmemLayout& S = *reinterpret_cast<SmemLayout*>(raw);

    const int tid  = threadIdx.x;
    const int wid  = tid >> 5;
    const int lane = tid & 31;

    // ---------------- init ----------------
    for (int j = tid; j < N; j += NT) {
        S.px[j]  = pts[3*j + 0];
        S.py[j]  = pts[3*j + 1];
        S.pz[j]  = pts[3*j + 2];
        S.slbl[j] = lbl[j];
        S.sdl[j]  = -1;
    }
    if (tid < 10) {
        float l = anchors[tid*3+0], w = anchors[tid*3+1], h = anchors[tid*3+2];
        S.amdxy[tid] = fmaxf(l, w);
        S.amdz[tid]  = h;
        S.ar2[tid]   = __fdiv_rn(norm3_xla(l, w, h), 2.0f);
    }
    if (tid == 0) {
        S.sdl[0] = 0;
        S.bci  = 0;
        S.bcls = lbl[0];
        S.blab = 0;
        S.bpcx = pts[0]; S.bpcy = pts[1]; S.bpcz = pts[2];
        S.bpn  = norm3_xla(pts[0], pts[1], pts[2]);
        S.ccls[0] = lbl[0];
    }
    __syncthreads();

    // per-thread register caches (strided mapping j = tid + k*NT)
    float mx[PER], my_[PER], mz_[PER];
    int   ml[PER], mydl[PER];
    bool  mv[PER];
#pragma unroll
    for (int k = 0; k < PER; ++k) {
        int j = tid + k * NT;
        mx[k] = S.px[j]; my_[k] = S.py[j]; mz_[k] = S.pz[j];
        ml[k] = S.slbl[j];
        mv[k] = false;
        mydl[k] = -1;
    }

    // serial-thread (tid 0) cluster state
    int    lab = 0;
    double sumx = (tid == 0) ? (double)S.bpcx : 0.0;
    double sumy = (tid == 0) ? (double)S.bpcy : 0.0;
    double sumz = (tid == 0) ? (double)S.bpcz : 0.0;
    int    cnt = 1;

    const float INF = __int_as_float(0x7f800000);
    const float THR = __int_as_float(ANGLE_THR_BITS);

    // ---------------- greedy scan: N-1 dependent steps ----------------
    for (int step = 0; step < N - 1; ++step) {
        // broadcast from previous serial update
        int   ci  = S.bci;
        float cxr = S.bpcx, cyr = S.bpcy, czr = S.bpcz;
        int   cls = S.bcls;
        int   curlab = S.blab;
        float pn  = S.bpn;

        // pass 1: dists (XLA bit-exact), masked min/max over unvisited,
        //         min of cos-argument over current-cluster members.
        float dreg[PER];
        float lmin = INF, lmax = -INF, lxm = INF;
#pragma unroll
        for (int k = 0; k < PER; ++k) {
            int j = tid + k * NT;
            if (ci == j) { mv[k] = true; mydl[k] = curlab; }
            float dx = __fsub_rn(mx[k],  cxr);   // p_j - p_cur (ref diff order)
            float dy = __fsub_rn(my_[k], cyr);
            float dz = __fsub_rn(mz_[k], czr);
            float d  = norm3_xla(dx, dy, dz);
            dreg[k] = d;
            if (!mv[k]) { lmin = fminf(lmin, d); lmax = fmaxf(lmax, d); }
            if (mydl[k] == curlab) {
                // dot = -(p_cur . diff), denom = |p_cur|*dist + 1e-8
                float dt = -(__fadd_rn(__fadd_rn(__fmul_rn(cxr, dx),
                                                 __fmul_rn(cyr, dy)),
                                       __fmul_rn(czr, dz)));
                float den = __fadd_rn(__fmul_rn(pn, d), 1e-8f);
                float xv  = __fdiv_rn(dt, den);
                lxm = fminf(lxm, xv);
            }
        }
#pragma unroll
        for (int o = 16; o > 0; o >>= 1) {
            lmin = fminf(lmin, __shfl_xor_sync(0xffffffffu, lmin, o));
            lmax = fmaxf(lmax, __shfl_xor_sync(0xffffffffu, lmax, o));
            lxm  = fminf(lxm,  __shfl_xor_sync(0xffffffffu, lxm,  o));
        }
        if (lane == 0) { S.rmin[wid] = lmin; S.rmax[wid] = lmax; S.rxm[wid] = lxm; }
        __syncthreads();
        if (wid == 0) {
            float a = S.rmin[lane], b = S.rmax[lane], c = S.rxm[lane];
#pragma unroll
            for (int o = 16; o > 0; o >>= 1) {
                a = fminf(a, __shfl_xor_sync(0xffffffffu, a, o));
                b = fmaxf(b, __shfl_xor_sync(0xffffffffu, b, o));
                c = fminf(c, __shfl_xor_sync(0xffffffffu, c, o));
            }
            if (lane == 0) { S.bdmin = a; S.bdmax = b; S.bxmin = c; }
        }
        __syncthreads();

        // pass 2: argmin of normalized cost (exact reference arithmetic)
        float dmin = S.bdmin;
        float Dn   = __fadd_rn(__fsub_rn(S.bdmax, dmin), 1e-8f);
        unsigned long long best = 0xFFFFFFFFFFFFFFFFull;
#pragma unroll
        for (int k = 0; k < PER; ++k) {
            if (!mv[k]) {
                float lcost = (ml[k] != cls) ? 1.0f : 0.0f;
                float c = __fadd_rn(__fdiv_rn(__fsub_rn(dreg[k], dmin), Dn), lcost);
                unsigned long long p =
                    ((unsigned long long)__float_as_uint(c) << 32) |
                    (unsigned)(tid + k * NT);
                if (p < best) best = p;
            }
        }
#pragma unroll
        for (int o = 16; o > 0; o >>= 1) {
            unsigned long long q = __shfl_xor_sync(0xffffffffu, best, o);
            if (q < best) best = q;
        }
        if (lane == 0) S.rpack[wid] = best;
        __syncthreads();
        if (wid == 0) {
            unsigned long long v = S.rpack[lane];
#pragma unroll
            for (int o = 16; o > 0; o >>= 1) {
                unsigned long long q = __shfl_xor_sync(0xffffffffu, v, o);
                if (q < v) v = q;
            }
            if (lane == 0) {
                int sel = (int)(v & 0xffffffffull);
                float cix = S.px[sel], ciy = S.py[sel], ciz = S.pz[sel];
                int   lci = S.slbl[sel];
                // d = p_cur - p_ci
                float dx = __fsub_rn(cxr, cix);
                float dy = __fsub_rn(cyr, ciy);
                float dz = __fsub_rn(czr, ciz);
                float dn = norm3_xla(dx, dy, dz);
                float cf = (float)cnt;
                float gx = __fdiv_rn((float)sumx, cf);
                float gy = __fdiv_rn((float)sumy, cf);
                float gz = __fdiv_rn((float)sumz, cf);
                float en = norm3_xla(__fsub_rn(gx, cix),
                                     __fsub_rn(gy, ciy),
                                     __fsub_rn(gz, ciz));
                float a0 = S.amdxy[cls], a2 = S.amdz[cls], r2 = S.ar2[cls];
                // angle condition: max over cm of acos(clip(x)) < thr  <=>
                // acos(clip(min x)) < thr   (acos, clip monotone)
                float xc = fminf(fmaxf(S.bxmin, -1.0f), 1.0f);
                bool angle_new = acos_xla(xc) < THR;
                bool newc = (fabsf(dx) > a0) | (fabsf(dy) > a0) | (fabsf(dz) > a2) |
                            angle_new |
                            (lci != cls) | (dn > r2) | (en > r2);
                if (newc) {
                    S.ccx[lab] = gx; S.ccy[lab] = gy; S.ccz[lab] = gz;
                    S.ccount[lab] = cnt;
                    lab += 1;
                    sumx = (double)cix; sumy = (double)ciy; sumz = (double)ciz; cnt = 1;
                    S.ccls[lab] = lci;
                } else {
                    sumx += (double)cix; sumy += (double)ciy; sumz += (double)ciz; cnt += 1;
                }
                S.sdl[sel] = lab;
                S.bci = sel; S.bcls = lci; S.blab = lab;
                S.bpcx = cix; S.bpcy = ciy; S.bpcz = ciz;
                S.bpn  = norm3_xla(cix, ciy, ciz);
            }
        }
        __syncthreads();
    }

    // flush final cluster
    if (tid == 0) {
        float cf = (float)cnt;
        S.ccx[lab] = __fdiv_rn((float)sumx, cf);
        S.ccy[lab] = __fdiv_rn((float)sumy, cf);
        S.ccz[lab] = __fdiv_rn((float)sumz, cf);
        S.ccount[lab] = cnt;
        S.bnc = lab;   // num_clusters (EXCLUSIVE of max label, matching reference)
    }
    __syncthreads();

    const int nc = S.bnc;

    // ---------------- stable descending sort by count (bitonic on packed keys) ----
    // key = (count << 12) | (4095 - cluster_id)  -> desc count, asc id on ties.
    unsigned* skey = reinterpret_cast<unsigned*>(S.px);  // px + part of py (dead now)
    for (int i = tid; i < 4096; i += NT) {
        unsigned key = 0;
        if (i < nc) key = ((unsigned)S.ccount[i] << 12) | (4095u - (unsigned)i);
        skey[i] = key;
    }
    for (int i = tid; i < N; i += NT) { S.remap[i] = i; S.keep[i] = 1; }
    __syncthreads();

    for (int k = 2; k <= 4096; k <<= 1) {
        for (int j = k >> 1; j > 0; j >>= 1) {
#pragma unroll
            for (int e = 0; e < 4; ++e) {
                int i = tid + e * NT;
                int ixj = i ^ j;
                if (ixj > i) {
                    unsigned a = skey[i], b = skey[ixj];
                    bool descBlock = ((i & k) == 0);
                    if (descBlock ? (a < b) : (a > b)) { skey[i] = b; skey[ixj] = a; }
                }
            }
            __syncthreads();
        }
    }
    for (int i = tid; i < N; i += NT)
        if (i < nc) S.order[i] = 4095 - (int)(skey[i] & 4095u);
    __syncthreads();

    // ---------------- group order-positions by cluster class (10 warps) ----------
    if (wid < 10) {
        int c = wid, total = 0;
        int limit = (nc + 31) & ~31;
        for (int s = lane; s < limit; s += 32) {
            bool m = (s < nc) && (S.ccls[S.order[s]] == c);
            unsigned bal = __ballot_sync(0xffffffffu, m);
            total += __popc(bal);
        }
        if (lane == 0) S.clsCount[c] = total;
    }
    __syncthreads();
    if (tid == 0) {
        int acc = 0;
        for (int c = 0; c < 10; ++c) { S.clsBase[c] = acc; acc += S.clsCount[c]; }
        S.clsBase[10] = acc;
    }
    __syncthreads();
    if (wid < 10) {
        int c = wid;
        int pos = S.clsBase[c];
        int limit = (nc + 31) & ~31;
        for (int s = lane; s < limit; s += 32) {
            bool m = (s < nc) && (S.ccls[S.order[s]] == c);
            unsigned bal = __ballot_sync(0xffffffffu, m);
            if (m) {
                int off = __popc(bal & ((1u << lane) - 1u));
                S.items[pos + off] = s;
            }
            pos += __popc(bal);
        }
    }
    __syncthreads();

    // ---------------- merge: 10 independent per-class sequential chains ----------
    if (wid < 10) {
        int c    = wid;
        int base = S.clsBase[c];
        int len  = S.clsBase[c + 1] - base;
        float r2c = S.ar2[c];
        for (int t = 0; t < len; ++t) {
            __syncwarp();
            int ipos = S.items[base + t];
            if (!S.keep[ipos]) continue;       // warp-uniform
            int idx = S.order[ipos];
            float ax = S.ccx[idx], ay = S.ccy[idx], az = S.ccz[idx];
            for (int s = t + 1 + lane; s < len; s += 32) {
                int jpos = S.items[base + s];
                if (S.keep[jpos]) {
                    int jidx = S.order[jpos];
                    float dd = norm3_xla(__fsub_rn(S.ccx[jidx], ax),
                                         __fsub_rn(S.ccy[jidx], ay),
                                         __fsub_rn(S.ccz[jidx], az));
                    if (dd < r2c) {
                        S.keep[jpos]  = 0;
                        S.remap[jidx] = idx;
                    }
                }
            }
        }
    }
    __syncthreads();

    // ---------------- output (labels as float32 — __output__ dtype) ----------
    for (int i = tid; i < N; i += NT)
        out[i] = (float)S.remap[S.sdl[i]];
}

extern "C" void kernel_launch(void* const* d_in, const int* in_sizes, int n_in,
                              void* d_out, int out_size)
{
    // Dispatch inputs by element count — robust to metadata ordering:
    //   frust_points: 3072*3 = 9216 f32
    //   frust_labels: 3072 i32
    //   anchors:      10*3  = 30   f32
    const float* pts     = nullptr;
    const int*   lbls    = nullptr;
    const float* anchors = nullptr;
    for (int i = 0; i < n_in; ++i) {
        if      (in_sizes[i] == N * 3) pts     = (const float*)d_in[i];
        else if (in_sizes[i] == N)     lbls    = (const int*)  d_in[i];
        else if (in_sizes[i] == 30)    anchors = (const float*)d_in[i];
    }
    // fallback to declared order if detection failed
    if (!pts)     pts     = (const float*)d_in[0];
    if (!lbls)    lbls    = (const int*)  d_in[1];
    if (!anchors) anchors = (const float*)d_in[2];

    float* out = (float*)d_out;
    (void)out_size;

    static bool attr_done = false;
    if (!attr_done) {
        cudaFuncSetAttribute(frustum_cluster_kernel,
                             cudaFuncAttributeMaxDynamicSharedMemorySize,
                             (int)sizeof(SmemLayout));
        attr_done = true;
    }
    frustum_cluster_kernel<<<1, NT, sizeof(SmemLayout)>>>(pts, lbls, anchors, out);
}